// round 15
// baseline (speedup 1.0000x reference)
#include <cuda_runtime.h>
#include <cuda_fp16.h>
#include <cstdint>
#include <math.h>

// ---------------- problem dims ----------------
#define B_DIM 128
#define T_DIM 64
#define E_DIM 300
#define H_DIM 2048
#define NCTA  128          // each CTA owns 16 H-cols x 4 gates = N=64 output cols
#define NKT   37           // K tiles of 64: 32 (h part) + 5 (x part, 320 padded)
#define KTH   32
#define A_TILE 16384       // A: 128 rows x 128B, SW128
#define W_TILE 8192        // W: 64 rows x 128B, SW128
#define STAGE_BYTES (A_TILE + W_TILE)   // 24576
#define RING_BYTES (2 * STAGE_BYTES)    // depth-2 ring per set
#define SC_OFF (8 * STAGE_BYTES)        // 196608 (4 rings x 2 stages)
#define GB_OFF (SC_OFF + 512)           // 197120: gates buffer 4 sets x 32 x 66 fl
#define SMEM_TOTAL (GB_OFF + 4 * 32 * 66 * 4)   // 230912
#define NTHR 512

// ---------------- device scratch ----------------
__device__ __align__(128) uint8_t g_W[(size_t)NCTA * NKT * W_TILE];   // ~37.9 MB
__device__ __align__(128) uint8_t g_A[2][(size_t)KTH * A_TILE];       // 2 x 512 KB
__device__ __align__(128) uint8_t g_X[T_DIM][(size_t)5 * A_TILE];     // 5 MB
__device__ float g_c[B_DIM * H_DIM];
__device__ float g_bsum[4 * H_DIM];
__device__ int g_bar;

// ---------------- PTX helpers ----------------
__device__ __forceinline__ uint32_t s2u(const void* p) {
    uint32_t a;
    asm("{ .reg .u64 t; cvta.to.shared.u64 t, %1; cvt.u32.u64 %0, t; }"
        : "=r"(a) : "l"(p));
    return a;
}

__device__ __forceinline__ void mbar_init(uint32_t a, uint32_t cnt) {
    asm volatile("mbarrier.init.shared.b64 [%0], %1;" :: "r"(a), "r"(cnt) : "memory");
}
__device__ __forceinline__ void mbar_arrive(uint32_t a) {
    asm volatile("mbarrier.arrive.shared.b64 _, [%0];" :: "r"(a) : "memory");
}
__device__ __forceinline__ void mbar_expect_tx(uint32_t a, uint32_t bytes) {
    asm volatile("mbarrier.arrive.expect_tx.shared.b64 _, [%0], %1;"
                 :: "r"(a), "r"(bytes) : "memory");
}
// expect-only (no arrival) — lets us split W-prefetch from the A fill
__device__ __forceinline__ void mbar_expect_only(uint32_t a, uint32_t bytes) {
    asm volatile("mbarrier.expect_tx.shared.b64 [%0], %1;"
                 :: "r"(a), "r"(bytes) : "memory");
}
__device__ __forceinline__ void mbar_wait(uint32_t a, uint32_t par) {
    asm volatile(
        "{\n\t.reg .pred P;\n\t"
        "W%=:\n\t"
        "mbarrier.try_wait.parity.acquire.cta.shared::cta.b64 P, [%0], %1, 0x989680;\n\t"
        "@P bra D%=;\n\t"
        "bra W%=;\n\t"
        "D%=:\n\t}" :: "r"(a), "r"(par) : "memory");
}

__device__ __forceinline__ void bulk_g2s(uint32_t dst, const void* src,
                                         uint32_t bytes, uint32_t mbar) {
    asm volatile(
        "cp.async.bulk.shared::cluster.global.mbarrier::complete_tx::bytes "
        "[%0], [%1], %2, [%3];"
        :: "r"(dst), "l"(src), "r"(bytes), "r"(mbar) : "memory");
}

__device__ __forceinline__ void ldsm4(uint32_t a[4], uint32_t addr) {
    asm volatile("ldmatrix.sync.aligned.m8n8.x4.shared.b16 {%0,%1,%2,%3}, [%4];"
                 : "=r"(a[0]), "=r"(a[1]), "=r"(a[2]), "=r"(a[3]) : "r"(addr));
}

__device__ __forceinline__ void mma16816(float c[4], const uint32_t a[4],
                                         uint32_t b0, uint32_t b1) {
    asm volatile(
        "mma.sync.aligned.m16n8k16.row.col.f32.f16.f16.f32 "
        "{%0,%1,%2,%3}, {%4,%5,%6,%7}, {%8,%9}, {%0,%1,%2,%3};"
        : "+f"(c[0]), "+f"(c[1]), "+f"(c[2]), "+f"(c[3])
        : "r"(a[0]), "r"(a[1]), "r"(a[2]), "r"(a[3]), "r"(b0), "r"(b1));
}

__device__ __forceinline__ uint32_t swz(uint32_t off) {
    return off ^ ((off >> 3) & 0x70);
}

// ---------------- prep kernels ----------------
__global__ void prep_W(const float* __restrict__ w_ih,
                       const float* __restrict__ w_hh) {
    int j = blockIdx.x / NKT;
    int kt = blockIdx.x % NKT;
    uint8_t* base = g_W + ((size_t)(j * NKT + kt)) * W_TILE;
    for (int idx = threadIdx.x; idx < 64 * 64; idx += blockDim.x) {
        int r = idx >> 6, c = idx & 63;
        int g = r >> 4;
        int wr = g * H_DIM + j * 16 + (r & 15);
        float v = 0.f;
        if (kt < KTH) {
            v = w_hh[(size_t)wr * H_DIM + kt * 64 + c];
        } else {
            int ke = (kt - KTH) * 64 + c;
            if (ke < E_DIM) v = w_ih[(size_t)wr * E_DIM + ke];
        }
        uint32_t sw = swz((uint32_t)(r * 128 + c * 2));
        *(__half*)(base + sw) = __float2half_rn(v);
    }
}

__global__ void prep_X(const int* __restrict__ input,
                       const float* __restrict__ embed) {
    int t = blockIdx.x / 5;
    int kt = blockIdx.x % 5;
    uint8_t* base = g_X[t] + (size_t)kt * A_TILE;
    for (int idx = threadIdx.x; idx < 128 * 64; idx += blockDim.x) {
        int row = idx >> 6, c = idx & 63;
        int ke = kt * 64 + c;
        float v = 0.f;
        if (ke < E_DIM) {
            int tok = input[row * T_DIM + t];
            v = embed[(size_t)tok * E_DIM + ke];
        }
        uint32_t sw = swz((uint32_t)(row * 128 + c * 2));
        *(__half*)(base + sw) = __float2half_rn(v);
    }
}

__global__ void prep_init(const float* __restrict__ b_ih,
                          const float* __restrict__ b_hh) {
    int i = blockIdx.x * blockDim.x + threadIdx.x;
    if (i < 131072) ((uint32_t*)g_A[0])[i] = 0u;   // h(0) fp16 tiles = 0
    if (i < 262144) g_c[i] = 0.f;
    if (i < 4 * H_DIM) g_bsum[i] = b_ih[i] + b_hh[i];
    if (i == 0) g_bar = 0;
}

// ---------------- persistent kernel ----------------
// 16 warps = 4 K-sets x 4 warps; set warp tile M64 x N32.
// Ring phases are CUMULATIVE across the 64 timesteps; a device-wide
// barrier separates steps; W halves of next step's stages prefetch early.
__global__ __launch_bounds__(NTHR, 1) void lstm_persist(float* __restrict__ out) {
    extern __shared__ __align__(1024) uint8_t smem[];
    const uint32_t sbase = s2u(smem);
    const int tid = threadIdx.x;
    const int lane = tid & 31;
    const int wid = tid >> 5;
    const int set = wid >> 2;      // 0..3
    const int lw = wid & 3;        // warp id within set
    const int warp_m = lw & 1;     // m0 = warp_m*64
    const int warp_n = lw >> 1;    // n0 = warp_n*32
    const int j0 = blockIdx.x * 16;

    const uint32_t full0 = sbase + SC_OFF;
    const uint32_t done0 = sbase + SC_OFF + 64;
    float* sb = (float*)(smem + SC_OFF + 128);   // 64 bias floats
    float* gb = (float*)(smem + GB_OFF);         // 4 x 32 x 66 partial gates

    if (tid == 0) {
        for (int s = 0; s < 8; s++) {
            mbar_init(full0 + 8 * s, 1);
            mbar_init(done0 + 8 * s, 4);
        }
    }
    if (tid >= 64 && tid < 128) {
        int i = tid - 64;
        sb[i] = g_bsum[(i >> 4) * H_DIM + j0 + (i & 15)];
    }
    __syncthreads();

    const uint8_t* wbuf = g_W + (size_t)blockIdx.x * NKT * W_TILE;
    const int c0 = set * 9;                 // sets 0-2: 9 chunks, set 3: 10
    const int nc = 9 + (set == 3 ? 1 : 0);
    const uint32_t ringb = sbase + (uint32_t)set * RING_BYTES;
    const uint32_t fullr = full0 + 16 * set;
    const uint32_t doner = done0 + 16 * set;
    const bool prod = (lane == 0) && (lw == 0);   // one per set

    // full fill of ring stage (cumi&1) with step-t chunk l of this set
    auto fillfull = [&](int cumi, const uint8_t* ab, const uint8_t* xb, int l) {
        uint32_t stg = ringb + (uint32_t)(cumi & 1) * STAGE_BYTES;
        uint32_t fb = fullr + 8 * (cumi & 1);
        mbar_expect_tx(fb, STAGE_BYTES);
        int c = c0 + l;
        const uint8_t* asrc = (c < KTH) ? (ab + (size_t)c * A_TILE)
                                        : (xb + (size_t)(c - KTH) * A_TILE);
        bulk_g2s(stg, asrc, A_TILE, fb);
        bulk_g2s(stg + A_TILE, wbuf + (size_t)c * W_TILE, W_TILE, fb);
    };

    if (prod) {
        fillfull(0, g_A[0], g_X[0], 0);
        fillfull(1, g_A[0], g_X[0], 1);
    }

    // per-lane ldmatrix offset components
    const int r8 = lane & 7;
    const int ii = lane >> 3;
    const int a_row = warp_m * 64 + (ii & 1) * 8 + r8;   // + mt*16
    const int a_cb = (ii >> 1) * 16;                     // + kt*32 (bytes)
    const int w_row = warp_n * 32 + (ii >> 1) * 8 + r8;  // + w*16
    const int w_cb = (ii & 1) * 16;                      // + kt*32 (bytes)

    const int ktile = j0 >> 6;
    const int cbase = j0 & 63;
    const int e_lrow = tid >> 4;       // epilogue row-in-pass 0..31
    const int e_cc = tid & 15;

    int cum = 0;
    for (int t = 0; t < T_DIM; t++) {
        const uint8_t* abuf = g_A[t & 1];
        const uint8_t* xbuf = g_X[t];

        float acc[4][4][4];
#pragma unroll
        for (int mt = 0; mt < 4; mt++)
#pragma unroll
            for (int p = 0; p < 4; p++)
#pragma unroll
                for (int q = 0; q < 4; q++) acc[mt][p][q] = 0.f;

        for (int l = 0; l < nc; l++, cum++) {
            int s = cum & 1;
            uint32_t stg = ringb + (uint32_t)s * STAGE_BYTES;
            mbar_wait(fullr + 8 * s, (cum >> 1) & 1);
#pragma unroll
            for (int kt = 0; kt < 4; kt++) {
                uint32_t aH[4][4], wH[2][4];
#pragma unroll
                for (int w = 0; w < 2; w++) {
                    uint32_t sw = swz((uint32_t)((w_row + w * 16) * 128 + w_cb + kt * 32));
                    ldsm4(wH[w], stg + A_TILE + sw);
                }
#pragma unroll
                for (int mt = 0; mt < 4; mt++) {
                    uint32_t sw = swz((uint32_t)((a_row + mt * 16) * 128 + a_cb + kt * 32));
                    ldsm4(aH[mt], stg + sw);
                }
#pragma unroll
                for (int mt = 0; mt < 4; mt++) {
#pragma unroll
                    for (int w = 0; w < 2; w++) {
#pragma unroll
                        for (int q = 0; q < 2; q++) {
                            mma16816(acc[mt][w * 2 + q], aH[mt],
                                     wH[w][2 * q], wH[w][2 * q + 1]);
                        }
                    }
                }
            }
            if (lane == 0) mbar_arrive(doner + 8 * s);
            if (prod && l + 2 < nc) {
                // stage of cum+2 == stage of cum; its done parity is (cum>>1)&1
                mbar_wait(doner + 8 * s, (cum >> 1) & 1);
                fillfull(cum + 2, abuf, xbuf, l + 2);
            }
        }

        // ---- cross-step W prefetch (A part waits for the barrier) ----
        if (prod && t + 1 < T_DIM) {
#pragma unroll
            for (int k = 0; k < 2; k++) {
                int cc = cum + k;
                int s2 = cc & 1;
                mbar_wait(doner + 8 * s2, ((cc - 2) >> 1) & 1);
                mbar_expect_only(fullr + 8 * s2, W_TILE);
                bulk_g2s(ringb + (uint32_t)s2 * STAGE_BYTES + A_TILE,
                         wbuf + (size_t)(c0 + k) * W_TILE, W_TILE,
                         fullr + 8 * s2);
            }
        }

        // ---- epilogue: 4 passes of M32 rows ----
        uint8_t* adst = g_A[(t + 1) & 1] + (size_t)ktile * A_TILE;
#pragma unroll
        for (int p = 0; p < 4; p++) {
            __syncthreads();
            if (warp_m == (p >> 1)) {
                int mtb = (p & 1) * 2;
#pragma unroll
                for (int mt2 = 0; mt2 < 2; mt2++) {
                    int mt = mtb + mt2;
                    int lrow = mt2 * 16 + (lane >> 2);
#pragma unroll
                    for (int q = 0; q < 4; q++) {
                        int ncol = warp_n * 32 + q * 8 + (lane & 3) * 2;
                        float* b = gb + set * (32 * 66) + lrow * 66 + ncol;
                        b[0] = acc[mt][q][0];
                        b[1] = acc[mt][q][1];
                        b[8 * 66] = acc[mt][q][2];
                        b[8 * 66 + 1] = acc[mt][q][3];
                    }
                }
            }
            __syncthreads();
            {
                int m = p * 32 + e_lrow;
                int base = e_lrow * 66 + e_cc;
                float xi = (gb[base] + gb[2112 + base])
                         + (gb[2 * 2112 + base] + gb[3 * 2112 + base]) + sb[e_cc];
                float xf = (gb[base + 16] + gb[2112 + base + 16])
                         + (gb[2 * 2112 + base + 16] + gb[3 * 2112 + base + 16])
                         + sb[16 + e_cc];
                float xg = (gb[base + 32] + gb[2112 + base + 32])
                         + (gb[2 * 2112 + base + 32] + gb[3 * 2112 + base + 32])
                         + sb[32 + e_cc];
                float xo = (gb[base + 48] + gb[2112 + base + 48])
                         + (gb[2 * 2112 + base + 48] + gb[3 * 2112 + base + 48])
                         + sb[48 + e_cc];
                float ig = 1.f / (1.f + __expf(-xi));
                float fg = 1.f / (1.f + __expf(-xf));
                float gg = 2.f / (1.f + __expf(-2.f * xg)) - 1.f;
                float og = 1.f / (1.f + __expf(-xo));
                int co = m * H_DIM + j0 + e_cc;
                float cn = fg * g_c[co] + ig * gg;
                g_c[co] = cn;
                float hv = og * (2.f / (1.f + __expf(-2.f * cn)) - 1.f);
                if (t < T_DIM - 1) {
                    uint32_t sw = swz((uint32_t)(m * 128 + (cbase + e_cc) * 2));
                    *(__half*)(adst + sw) = __float2half_rn(hv);
                } else {
                    out[m * H_DIM + j0 + e_cc] = hv;
                }
            }
        }

        if (t + 1 < T_DIM) {
            // ---- device-wide barrier ----
            asm volatile("fence.proxy.async;" ::: "memory");
            __syncthreads();
            if (tid == 0) {
                asm volatile("red.release.gpu.global.add.s32 [%0], 1;"
                             :: "l"(&g_bar) : "memory");
                int target = NCTA * (t + 1);
                int v;
                do {
                    asm volatile("ld.acquire.gpu.global.s32 %0, [%1];"
                                 : "=r"(v) : "l"(&g_bar) : "memory");
                } while (v < target);
            }
            __syncthreads();
            // ---- A fills for next step's first two chunks ----
            if (prod) {
                const uint8_t* nab = g_A[(t + 1) & 1];
                const uint8_t* nxb = g_X[t + 1];
#pragma unroll
                for (int k = 0; k < 2; k++) {
                    int cc = cum + k;
                    int s2 = cc & 1;
                    uint32_t fb = fullr + 8 * s2;
                    mbar_expect_tx(fb, A_TILE);   // the single arrival
                    int c = c0 + k;
                    const uint8_t* asrc = (c < KTH)
                        ? (nab + (size_t)c * A_TILE)
                        : (nxb + (size_t)(c - KTH) * A_TILE);
                    bulk_g2s(ringb + (uint32_t)s2 * STAGE_BYTES, asrc, A_TILE, fb);
                }
            }
        }
    }
}

// ---------------- host ----------------
extern "C" void kernel_launch(void* const* d_in, const int* in_sizes, int n_in,
                              void* d_out, int out_size) {
    const int* input = (const int*)d_in[0];
    const float* embed = (const float*)d_in[1];
    const float* w_ih = (const float*)d_in[2];
    const float* w_hh = (const float*)d_in[3];
    const float* b_ih = (const float*)d_in[4];
    const float* b_hh = (const float*)d_in[5];
    float* out = (float*)d_out;

    cudaFuncSetAttribute(lstm_persist, cudaFuncAttributeMaxDynamicSharedMemorySize,
                         SMEM_TOTAL);

    prep_W<<<NCTA * NKT, 256>>>(w_ih, w_hh);
    prep_X<<<T_DIM * 5, 256>>>(input, embed);
    prep_init<<<1024, 256>>>(b_ih, b_hh);

    lstm_persist<<<NCTA, NTHR, SMEM_TOTAL>>>(out);
}